// round 1
// baseline (speedup 1.0000x reference)
#include <cuda_runtime.h>
#include <math.h>

#define BB   2
#define SS   2048
#define DD   1024
#define HH   8
#define EE   4
#define DHH  128
#define TOK  (BB*SS)                    /* 4096 tokens */
#define SCALE 0.29730177875068026f      /* 128^-0.25 */

/* ------------------------------------------------------------------ */
/* scratch (device globals; no allocation allowed)                     */
/* ------------------------------------------------------------------ */
__device__ float g_q[TOK * DD];        /* [b,h,s,dh] */
__device__ float g_k[TOK * DD];        /* [b,h,s,dh] */
__device__ float g_v[TOK * DD];        /* [b,h,s,dh] */
__device__ float g_res[TOK * DD];      /* [t, h, dh] token-major */
__device__ float g_gv[TOK * HH * EE];  /* dense V gates (0 if unselected) */
__device__ float g_go[TOK * HH * EE];  /* dense O gates */

/* ------------------------------------------------------------------ */
/* Gates: sigmoid(x @ sel.T), top-2 of 4 per head -> dense gate array  */
/* grid (TOK/8, 2), 256 threads; one warp per token; lane = h*4+e      */
/* ------------------------------------------------------------------ */
__global__ void gates_kernel(const float* __restrict__ k_src,
                             const float* __restrict__ sel_v,
                             const float* __restrict__ q_src,
                             const float* __restrict__ sel_o) {
    int w = threadIdx.x >> 5;
    int lane = threadIdx.x & 31;
    int t = blockIdx.x * 8 + w;

    const float* x;  const float* sel;  float* out;
    if (blockIdx.y == 0) { x = k_src; sel = sel_v; out = g_gv; }
    else                 { x = q_src; sel = sel_o; out = g_go; }

    const float4* xr = (const float4*)(x + (size_t)t * DD);
    const float4* sr = (const float4*)(sel + (size_t)lane * DD);
    float acc = 0.f;
#pragma unroll 8
    for (int i = 0; i < DD / 4; i++) {
        float4 a = xr[i], b = sr[i];
        acc += a.x * b.x + a.y * b.y + a.z * b.z + a.w * b.w;
    }
    float g = 1.f / (1.f + __expf(-acc));

    __shared__ float sh[8][32];
    sh[w][lane] = g;
    __syncwarp();

    if (lane < HH) {
        float vv[4];
        vv[0] = sh[w][lane * 4 + 0];
        vv[1] = sh[w][lane * 4 + 1];
        vv[2] = sh[w][lane * 4 + 2];
        vv[3] = sh[w][lane * 4 + 3];
        int i1 = 0; float m1 = vv[0];
#pragma unroll
        for (int e = 1; e < 4; e++) if (vv[e] > m1) { m1 = vv[e]; i1 = e; }
        int i2 = -1; float m2 = -1e30f;
#pragma unroll
        for (int e = 0; e < 4; e++) if (e != i1 && vv[e] > m2) { m2 = vv[e]; i2 = e; }
#pragma unroll
        for (int e = 0; e < 4; e++)
            out[(size_t)t * 32 + lane * 4 + e] = (e == i1 || e == i2) ? vv[e] : 0.f;
    }
}

/* ------------------------------------------------------------------ */
/* Generic 128x128x16 SGEMM, 256 threads, 8x8 per thread.              */
/* MODE 0: Q proj   C = q_src @ Wq^T * s   -> g_q  [b,h,s,dh]          */
/* MODE 1: K proj   C = k_src @ Wk^T * s   -> g_k                      */
/* MODE 2: V build  per h: A[t,(e,k)] = v_src[t,k]*gv[t,h,e],          */
/*                  B = Wv[h] flat [4096,128]          -> g_v          */
/* MODE 3: O build  A[t,(h,e,dh)] = res[t,h,dh]*go[t,h,e],             */
/*                  B = Wo flat [4096,1024]            -> out          */
/* ------------------------------------------------------------------ */
template <int MODE>
__global__ void __launch_bounds__(256, 2)
sgemm_kernel(const float* __restrict__ A,
             const float* __restrict__ Bm,
             float* __restrict__ C) {
    constexpr int KT = (MODE <= 1) ? 1024 : 4096;
    constexpr int SAST = 132;  /* padded shared row stride */

    __shared__ float As[16 * SAST];
    __shared__ float Bs[16 * SAST];

    int tid = threadIdx.x;
    int tx = tid & 15, ty = tid >> 4;
    int row0 = blockIdx.y * 128;
    int col0 = blockIdx.x * 128;
    int hz = blockIdx.z;  /* head, MODE 2 only */

    const float* gates = (MODE == 2) ? g_gv : g_go;
    const float* Bp = Bm;
    if (MODE == 2) Bp = Bm + (size_t)hz * (EE * DD * DHH);

    float acc[8][8];
#pragma unroll
    for (int i = 0; i < 8; i++)
#pragma unroll
        for (int j = 0; j < 8; j++) acc[i][j] = 0.f;

    for (int k0 = 0; k0 < KT; k0 += 16) {
        /* ---- load A tile (transposed to As[k][m]) ---- */
#pragma unroll
        for (int li = 0; li < 2; li++) {
            int ar = (tid >> 2) + li * 64;
            int ac = (tid & 3) * 4;
            int kg = k0 + ac;
            const float* src;
            float gmul = 1.f;
            if (MODE <= 1) {
                src = A + (size_t)(row0 + ar) * 1024 + kg;
            } else if (MODE == 2) {
                int e = kg >> 10;
                int kin = kg & 1023;
                src = A + (size_t)(row0 + ar) * 1024 + kin;
                gmul = gates[(size_t)(row0 + ar) * 32 + hz * 4 + e];
            } else {
                int hh = kg >> 9;
                int e = (kg >> 7) & 3;
                int dh = kg & 127;
                src = g_res + (size_t)(row0 + ar) * 1024 + hh * 128 + dh;
                gmul = gates[(size_t)(row0 + ar) * 32 + hh * 4 + e];
            }
            float4 x = *(const float4*)src;
            x.x *= gmul; x.y *= gmul; x.z *= gmul; x.w *= gmul;
            As[(ac + 0) * SAST + ar] = x.x;
            As[(ac + 1) * SAST + ar] = x.y;
            As[(ac + 2) * SAST + ar] = x.z;
            As[(ac + 3) * SAST + ar] = x.w;
        }
        /* ---- load B tile ---- */
        if (MODE <= 1) {
            /* B is [N,K] row-major (W): transpose into Bs[k][n] */
#pragma unroll
            for (int li = 0; li < 2; li++) {
                int br = (tid >> 2) + li * 64;
                int bc = (tid & 3) * 4;
                float4 x = *(const float4*)(Bp + (size_t)(col0 + br) * 1024 + k0 + bc);
                Bs[(bc + 0) * SAST + br] = x.x;
                Bs[(bc + 1) * SAST + br] = x.y;
                Bs[(bc + 2) * SAST + br] = x.z;
                Bs[(bc + 3) * SAST + br] = x.w;
            }
        } else {
            /* B is [K,N] row-major: direct copy */
            constexpr int NLD = (MODE == 2) ? 128 : 1024;
#pragma unroll
            for (int li = 0; li < 2; li++) {
                int kr = (tid >> 5) + li * 8;
                int nc = (tid & 31) * 4;
                float4 x = *(const float4*)(Bp + (size_t)(k0 + kr) * NLD + col0 + nc);
                *(float4*)&Bs[kr * SAST + nc] = x;
            }
        }
        __syncthreads();

#pragma unroll
        for (int kk = 0; kk < 16; kk++) {
            float a[8], b[8];
            *(float4*)&a[0] = *(const float4*)&As[kk * SAST + ty * 8];
            *(float4*)&a[4] = *(const float4*)&As[kk * SAST + ty * 8 + 4];
            *(float4*)&b[0] = *(const float4*)&Bs[kk * SAST + tx * 4];
            *(float4*)&b[4] = *(const float4*)&Bs[kk * SAST + 64 + tx * 4];
#pragma unroll
            for (int i = 0; i < 8; i++)
#pragma unroll
                for (int j = 0; j < 8; j++) acc[i][j] += a[i] * b[j];
        }
        __syncthreads();
    }

    /* ---- store ---- */
#pragma unroll
    for (int i = 0; i < 8; i++) {
        int t = row0 + ty * 8 + i;
        int bidx = t >> 11, sidx = t & 2047;
#pragma unroll
        for (int jg = 0; jg < 2; jg++) {
            int ncol = col0 + jg * 64 + tx * 4;
            float4 o;
            o.x = acc[i][jg * 4 + 0]; o.y = acc[i][jg * 4 + 1];
            o.z = acc[i][jg * 4 + 2]; o.w = acc[i][jg * 4 + 3];
            if (MODE <= 1) {
                o.x *= SCALE; o.y *= SCALE; o.z *= SCALE; o.w *= SCALE;
                int hh = ncol >> 7, dh = ncol & 127;
                float* dst = (MODE == 0) ? g_q : g_k;
                *(float4*)&dst[(((size_t)bidx * HH + hh) * SS + sidx) * DHH + dh] = o;
            } else if (MODE == 2) {
                *(float4*)&g_v[(((size_t)bidx * HH + hz) * SS + sidx) * DHH + ncol] = o;
            } else {
                *(float4*)&C[(size_t)t * 1024 + ncol] = o;
            }
        }
    }
}

/* ------------------------------------------------------------------ */
/* Flash attention fp32: BQ=64, BKV=64, 256 threads                    */
/* grid (S/64, B*H); writes g_res[t, h, dh]                            */
/* ------------------------------------------------------------------ */
#define QST 129
#define SST 65
#define ATTN_SMEM_FLOATS (2 * 64 * QST + 64 * SST + 3 * 64)
#define ATTN_SMEM_BYTES  (ATTN_SMEM_FLOATS * 4)

__global__ void __launch_bounds__(256, 2) attn_kernel() {
    extern __shared__ float sm[];
    float* Qs  = sm;
    float* KVs = sm + 64 * QST;
    float* Ssm = sm + 2 * 64 * QST;
    float* Ms  = Ssm + 64 * SST;
    float* Ls  = Ms + 64;
    float* Cs  = Ls + 64;

    int tid = threadIdx.x;
    int tx = tid & 15, ty = tid >> 4;
    int bh = blockIdx.y;
    int q0 = blockIdx.x * 64;

    const float* qbase = g_q + (size_t)bh * SS * DHH;
    const float* kbase = g_k + (size_t)bh * SS * DHH;
    const float* vbase = g_v + (size_t)bh * SS * DHH;

    /* load Q tile */
#pragma unroll
    for (int it = 0; it < 8; it++) {
        int idx = it * 256 + tid;
        int r = idx >> 5, c4 = (idx & 31) * 4;
        float4 x = *(const float4*)(qbase + (size_t)(q0 + r) * DHH + c4);
        Qs[r * QST + c4 + 0] = x.x; Qs[r * QST + c4 + 1] = x.y;
        Qs[r * QST + c4 + 2] = x.z; Qs[r * QST + c4 + 3] = x.w;
    }
    if (tid < 64) { Ms[tid] = -1e30f; Ls[tid] = 0.f; }

    float o[4][8];
#pragma unroll
    for (int i = 0; i < 4; i++)
#pragma unroll
        for (int j = 0; j < 8; j++) o[i][j] = 0.f;

    __syncthreads();

    for (int kv0 = 0; kv0 < SS; kv0 += 64) {
        /* load K tile */
#pragma unroll
        for (int it = 0; it < 8; it++) {
            int idx = it * 256 + tid;
            int r = idx >> 5, c4 = (idx & 31) * 4;
            float4 x = *(const float4*)(kbase + (size_t)(kv0 + r) * DHH + c4);
            KVs[r * QST + c4 + 0] = x.x; KVs[r * QST + c4 + 1] = x.y;
            KVs[r * QST + c4 + 2] = x.z; KVs[r * QST + c4 + 3] = x.w;
        }
        __syncthreads();

        /* scores: rows ty*4+i, cols tx*4+j */
        float s[4][4];
#pragma unroll
        for (int i = 0; i < 4; i++)
#pragma unroll
            for (int j = 0; j < 4; j++) s[i][j] = 0.f;

#pragma unroll 4
        for (int d = 0; d < 128; d++) {
            float a[4], b[4];
#pragma unroll
            for (int i = 0; i < 4; i++) a[i] = Qs[(ty * 4 + i) * QST + d];
#pragma unroll
            for (int j = 0; j < 4; j++) b[j] = KVs[(tx * 4 + j) * QST + d];
#pragma unroll
            for (int i = 0; i < 4; i++)
#pragma unroll
                for (int j = 0; j < 4; j++) s[i][j] += a[i] * b[j];
        }
        __syncthreads();  /* K reads done; safe to overwrite KVs */

        /* write scores, load V */
#pragma unroll
        for (int i = 0; i < 4; i++) {
            float4 v4; v4.x = s[i][0]; v4.y = s[i][1]; v4.z = s[i][2]; v4.w = s[i][3];
            Ssm[(ty * 4 + i) * SST + tx * 4 + 0] = v4.x;
            Ssm[(ty * 4 + i) * SST + tx * 4 + 1] = v4.y;
            Ssm[(ty * 4 + i) * SST + tx * 4 + 2] = v4.z;
            Ssm[(ty * 4 + i) * SST + tx * 4 + 3] = v4.w;
        }
#pragma unroll
        for (int it = 0; it < 8; it++) {
            int idx = it * 256 + tid;
            int r = idx >> 5, c4 = (idx & 31) * 4;
            float4 x = *(const float4*)(vbase + (size_t)(kv0 + r) * DHH + c4);
            KVs[r * QST + c4 + 0] = x.x; KVs[r * QST + c4 + 1] = x.y;
            KVs[r * QST + c4 + 2] = x.z; KVs[r * QST + c4 + 3] = x.w;
        }
        __syncthreads();

        /* online softmax stats: 4 threads per row */
        {
            int row = tid >> 2, seg = tid & 3;
            float mloc = -1e30f;
#pragma unroll 4
            for (int c = seg * 16; c < seg * 16 + 16; c++)
                mloc = fmaxf(mloc, Ssm[row * SST + c]);
            mloc = fmaxf(mloc, __shfl_xor_sync(0xffffffffu, mloc, 1));
            mloc = fmaxf(mloc, __shfl_xor_sync(0xffffffffu, mloc, 2));
            float mold = Ms[row];
            float mnew = fmaxf(mold, mloc);
            float corr = __expf(mold - mnew);
            float lsum = 0.f;
#pragma unroll 4
            for (int c = seg * 16; c < seg * 16 + 16; c++) {
                float p = __expf(Ssm[row * SST + c] - mnew);
                Ssm[row * SST + c] = p;
                lsum += p;
            }
            lsum += __shfl_xor_sync(0xffffffffu, lsum, 1);
            lsum += __shfl_xor_sync(0xffffffffu, lsum, 2);
            if (seg == 0) {
                Ms[row] = mnew;
                Cs[row] = corr;
                Ls[row] = Ls[row] * corr + lsum;
            }
        }
        __syncthreads();

        /* rescale accumulators, then O += P @ V */
        float cr[4];
#pragma unroll
        for (int i = 0; i < 4; i++) cr[i] = Cs[ty * 4 + i];
#pragma unroll
        for (int i = 0; i < 4; i++)
#pragma unroll
            for (int j = 0; j < 8; j++) o[i][j] *= cr[i];

#pragma unroll 2
        for (int kk = 0; kk < 64; kk++) {
            float p[4], v[8];
#pragma unroll
            for (int i = 0; i < 4; i++) p[i] = Ssm[(ty * 4 + i) * SST + kk];
#pragma unroll
            for (int j = 0; j < 4; j++) v[j] = KVs[kk * QST + tx * 4 + j];
#pragma unroll
            for (int j = 0; j < 4; j++) v[4 + j] = KVs[kk * QST + 64 + tx * 4 + j];
#pragma unroll
            for (int i = 0; i < 4; i++)
#pragma unroll
                for (int j = 0; j < 8; j++) o[i][j] += p[i] * v[j];
        }
        __syncthreads();  /* PV reads done before next K load */
    }

    /* epilogue: normalize, store to g_res[t, h, dh] */
    int bidx = bh >> 3, hh = bh & 7;
#pragma unroll
    for (int i = 0; i < 4; i++) {
        float linv = 1.f / Ls[ty * 4 + i];
        int r = q0 + ty * 4 + i;
        size_t t = (size_t)bidx * SS + r;
#pragma unroll
        for (int jg = 0; jg < 2; jg++) {
            float4 ov;
            ov.x = o[i][jg * 4 + 0] * linv; ov.y = o[i][jg * 4 + 1] * linv;
            ov.z = o[i][jg * 4 + 2] * linv; ov.w = o[i][jg * 4 + 3] * linv;
            *(float4*)&g_res[t * 1024 + hh * 128 + jg * 64 + tx * 4] = ov;
        }
    }
}

/* ------------------------------------------------------------------ */
extern "C" void kernel_launch(void* const* d_in, const int* in_sizes, int n_in,
                              void* d_out, int out_size) {
    (void)in_sizes; (void)n_in; (void)out_size;
    const float* q_src = (const float*)d_in[0];
    const float* k_src = (const float*)d_in[1];
    const float* v_src = (const float*)d_in[2];
    const float* Wq    = (const float*)d_in[3];
    const float* Wk    = (const float*)d_in[4];
    const float* Wv    = (const float*)d_in[5];
    const float* Wo    = (const float*)d_in[6];
    const float* sel_v = (const float*)d_in[7];
    const float* sel_o = (const float*)d_in[8];
    float* out = (float*)d_out;

    cudaFuncSetAttribute(attn_kernel,
                         cudaFuncAttributeMaxDynamicSharedMemorySize,
                         ATTN_SMEM_BYTES);

    gates_kernel<<<dim3(TOK / 8, 2), 256>>>(k_src, sel_v, q_src, sel_o);
    sgemm_kernel<0><<<dim3(8, 32), 256>>>(q_src, Wq, nullptr);
    sgemm_kernel<1><<<dim3(8, 32), 256>>>(k_src, Wk, nullptr);
    sgemm_kernel<2><<<dim3(1, 32, 8), 256>>>(v_src, Wv, nullptr);
    attn_kernel<<<dim3(SS / 64, BB * HH), 256, ATTN_SMEM_BYTES>>>();
    sgemm_kernel<3><<<dim3(8, 32), 256>>>(nullptr, Wo, out);
}

// round 4
// speedup vs baseline: 2.1601x; 2.1601x over previous
#include <cuda_runtime.h>
#include <cuda_bf16.h>
#include <cstdint>
#include <math.h>

#define BB   2
#define SS   2048
#define DD   1024
#define HH   8
#define EE   4
#define DHH  128
#define TOK  (BB*SS)
#define SCALE 0.29730177875068026f      /* 128^-0.25 */

/* ------------------------------------------------------------------ */
/* scratch                                                             */
/* ------------------------------------------------------------------ */
__device__ float g_q[TOK * DD];        /* [b,h,s,dh] */
__device__ float g_k[TOK * DD];
__device__ float g_v[TOK * DD];
__device__ float g_res[TOK * DD];      /* [t, h*128+dh] */
__device__ float g_gv[TOK * HH * EE];
__device__ float g_go[TOK * HH * EE];

/* ------------------------------------------------------------------ */
/* helpers                                                             */
/* ------------------------------------------------------------------ */
__device__ __forceinline__ uint32_t smem_u32(const void* p) {
    return (uint32_t)__cvta_generic_to_shared(p);
}
__device__ __forceinline__ void ldsm4(uint32_t* r, uint32_t a) {
    asm volatile("ldmatrix.sync.aligned.m8n8.x4.shared.b16 {%0,%1,%2,%3}, [%4];"
                 : "=r"(r[0]), "=r"(r[1]), "=r"(r[2]), "=r"(r[3]) : "r"(a));
}
__device__ __forceinline__ void ldsm4t(uint32_t* r, uint32_t a) {
    asm volatile("ldmatrix.sync.aligned.m8n8.x4.trans.shared.b16 {%0,%1,%2,%3}, [%4];"
                 : "=r"(r[0]), "=r"(r[1]), "=r"(r[2]), "=r"(r[3]) : "r"(a));
}
__device__ __forceinline__ void mma16816(float* d, const uint32_t* a, const uint32_t* b) {
    asm volatile(
        "mma.sync.aligned.m16n8k16.row.col.f32.bf16.bf16.f32 "
        "{%0,%1,%2,%3}, {%4,%5,%6,%7}, {%8,%9}, {%0,%1,%2,%3};"
        : "+f"(d[0]), "+f"(d[1]), "+f"(d[2]), "+f"(d[3])
        : "r"(a[0]), "r"(a[1]), "r"(a[2]), "r"(a[3]), "r"(b[0]), "r"(b[1]));
}
__device__ __forceinline__ uint32_t packbf(float x, float y) {
    __nv_bfloat162 t = __floats2bfloat162_rn(x, y);
    return *reinterpret_cast<uint32_t*>(&t);
}
__device__ __forceinline__ void split_pair(float x, float y, uint32_t& h, uint32_t& l) {
    float hx = __bfloat162float(__float2bfloat16(x));
    float hy = __bfloat162float(__float2bfloat16(y));
    h = packbf(hx, hy);
    l = packbf(x - hx, y - hy);
}

/* ------------------------------------------------------------------ */
/* Gates: sigmoid(x @ sel.T), top-2 of 4 per head -> dense gate array  */
/* ------------------------------------------------------------------ */
__global__ void gates_kernel(const float* __restrict__ k_src,
                             const float* __restrict__ sel_v,
                             const float* __restrict__ q_src,
                             const float* __restrict__ sel_o) {
    int w = threadIdx.x >> 5;
    int lane = threadIdx.x & 31;
    int t = blockIdx.x * 8 + w;

    const float* x; const float* sel; float* out;
    if (blockIdx.y == 0) { x = k_src; sel = sel_v; out = g_gv; }
    else                 { x = q_src; sel = sel_o; out = g_go; }

    const float4* xr = (const float4*)(x + (size_t)t * DD);
    const float4* sr = (const float4*)(sel + (size_t)lane * DD);
    float acc = 0.f;
#pragma unroll 8
    for (int i = 0; i < DD / 4; i++) {
        float4 a = xr[i], b = sr[i];
        acc += a.x * b.x + a.y * b.y + a.z * b.z + a.w * b.w;
    }
    float g = 1.f / (1.f + __expf(-acc));

    __shared__ float sh[8][32];
    sh[w][lane] = g;
    __syncwarp();

    if (lane < HH) {
        float vv[4];
#pragma unroll
        for (int e = 0; e < 4; e++) vv[e] = sh[w][lane * 4 + e];
        int i1 = 0; float m1 = vv[0];
#pragma unroll
        for (int e = 1; e < 4; e++) if (vv[e] > m1) { m1 = vv[e]; i1 = e; }
        int i2 = -1; float m2 = -1e30f;
#pragma unroll
        for (int e = 0; e < 4; e++) if (e != i1 && vv[e] > m2) { m2 = vv[e]; i2 = e; }
#pragma unroll
        for (int e = 0; e < 4; e++)
            out[(size_t)t * 32 + lane * 4 + e] = (e == i1 || e == i2) ? vv[e] : 0.f;
    }
}

/* ------------------------------------------------------------------ */
/* Tensor-core GEMM, block 128x128, Kc=32, 8 warps (4x2), split bf16.  */
/* MODE 0: Q proj, 1: K proj, 2: V expert build, 3: O expert build     */
/* ------------------------------------------------------------------ */
#define ASTR 40     /* [128][32] tiles, padded */
#define BSTR 136    /* [32][128] tiles, padded */

template <int MODE>
__global__ void __launch_bounds__(256)
tc_gemm(const float* __restrict__ A,
        const float* __restrict__ Bm,
        float* __restrict__ C) {
    constexpr int KT = (MODE <= 1) ? 1024 : 4096;

    __shared__ __nv_bfloat16 Ah[128 * ASTR];
    __shared__ __nv_bfloat16 Al[128 * ASTR];
    /* mode 0/1: B as [n=128][k=32] stride ASTR; mode 2/3: [k=32][n=128] stride BSTR */
    __shared__ __nv_bfloat16 Bh[128 * ASTR];
    __shared__ __nv_bfloat16 Bl[128 * ASTR];

    int tid = threadIdx.x;
    int warp = tid >> 5, lane = tid & 31;
    int wm = warp & 3, wn = warp >> 2;          /* 4 x 2 warp grid */
    int row0 = blockIdx.y * 128;
    int col0 = blockIdx.x * 128;
    int hz = blockIdx.z;

    const float* gates = (MODE == 2) ? g_gv : g_go;
    const float* Bp = Bm;
    if (MODE == 2) Bp = Bm + (size_t)hz * (EE * DD * DHH);

    float d[2][8][4];
#pragma unroll
    for (int i = 0; i < 2; i++)
#pragma unroll
        for (int j = 0; j < 8; j++)
#pragma unroll
            for (int c = 0; c < 4; c++) d[i][j][c] = 0.f;

    for (int k0 = 0; k0 < KT; k0 += 32) {
        /* ---- stage A tile (with gating) ---- */
#pragma unroll
        for (int it = 0; it < 4; it++) {
            int idx = it * 256 + tid;
            int r = idx >> 3, c4 = (idx & 7) * 4;
            int kg = k0 + c4;
            int rt = row0 + r;
            const float* src;
            float gm = 1.f;
            if (MODE <= 1) {
                src = A + (size_t)rt * 1024 + kg;
            } else if (MODE == 2) {
                src = A + (size_t)rt * 1024 + (kg & 1023);
                gm = gates[(size_t)rt * 32 + hz * 4 + (kg >> 10)];
            } else {
                int hh = kg >> 9, e = (kg >> 7) & 3, dh = kg & 127;
                src = g_res + (size_t)rt * 1024 + hh * 128 + dh;
                gm = gates[(size_t)rt * 32 + hh * 4 + e];
            }
            float4 x = *(const float4*)src;
            x.x *= gm; x.y *= gm; x.z *= gm; x.w *= gm;
            uint32_t h0, l0, h1, l1;
            split_pair(x.x, x.y, h0, l0);
            split_pair(x.z, x.w, h1, l1);
            *(uint32_t*)&Ah[r * ASTR + c4] = h0;
            *(uint32_t*)&Ah[r * ASTR + c4 + 2] = h1;
            *(uint32_t*)&Al[r * ASTR + c4] = l0;
            *(uint32_t*)&Al[r * ASTR + c4 + 2] = l1;
        }
        /* ---- stage B tile ---- */
        if (MODE <= 1) {
#pragma unroll
            for (int it = 0; it < 4; it++) {
                int idx = it * 256 + tid;
                int r = idx >> 3, c4 = (idx & 7) * 4;
                float4 x = *(const float4*)(Bp + (size_t)(col0 + r) * 1024 + k0 + c4);
                uint32_t h0, l0, h1, l1;
                split_pair(x.x, x.y, h0, l0);
                split_pair(x.z, x.w, h1, l1);
                *(uint32_t*)&Bh[r * ASTR + c4] = h0;
                *(uint32_t*)&Bh[r * ASTR + c4 + 2] = h1;
                *(uint32_t*)&Bl[r * ASTR + c4] = l0;
                *(uint32_t*)&Bl[r * ASTR + c4 + 2] = l1;
            }
        } else {
            constexpr int NLD = (MODE == 2) ? 128 : 1024;
#pragma unroll
            for (int it = 0; it < 4; it++) {
                int idx = it * 256 + tid;
                int kr = idx >> 5, c4 = (idx & 31) * 4;
                float4 x = *(const float4*)(Bp + (size_t)(k0 + kr) * NLD + col0 + c4);
                uint32_t h0, l0, h1, l1;
                split_pair(x.x, x.y, h0, l0);
                split_pair(x.z, x.w, h1, l1);
                *(uint32_t*)&Bh[kr * BSTR + c4] = h0;
                *(uint32_t*)&Bh[kr * BSTR + c4 + 2] = h1;
                *(uint32_t*)&Bl[kr * BSTR + c4] = l0;
                *(uint32_t*)&Bl[kr * BSTR + c4 + 2] = l1;
            }
        }
        __syncthreads();

        /* ---- MMAs ---- */
#pragma unroll
        for (int ks = 0; ks < 2; ks++) {
            uint32_t ah[2][4], al[2][4];
#pragma unroll
            for (int mf = 0; mf < 2; mf++) {
                int off = (wm * 32 + mf * 16 + (lane & 15)) * ASTR + ks * 16 + (lane >> 4) * 8;
                ldsm4(ah[mf], smem_u32(&Ah[off]));
                ldsm4(al[mf], smem_u32(&Al[off]));
            }
            uint32_t bfh[16], bfl[16];
            if (MODE <= 1) {
#pragma unroll
                for (int nf2 = 0; nf2 < 4; nf2++) {
                    int off = (wn * 64 + nf2 * 16 + (lane & 15)) * ASTR + ks * 16 + (lane >> 4) * 8;
                    uint32_t r[4];
                    ldsm4(r, smem_u32(&Bh[off]));
                    bfh[nf2 * 4 + 0] = r[0]; bfh[nf2 * 4 + 1] = r[2];
                    bfh[nf2 * 4 + 2] = r[1]; bfh[nf2 * 4 + 3] = r[3];
                    ldsm4(r, smem_u32(&Bl[off]));
                    bfl[nf2 * 4 + 0] = r[0]; bfl[nf2 * 4 + 1] = r[2];
                    bfl[nf2 * 4 + 2] = r[1]; bfl[nf2 * 4 + 3] = r[3];
                }
            } else {
#pragma unroll
                for (int nf2 = 0; nf2 < 4; nf2++) {
                    int off = (ks * 16 + (lane & 15)) * BSTR + wn * 64 + nf2 * 16 + (lane >> 4) * 8;
                    uint32_t r[4];
                    ldsm4t(r, smem_u32(&Bh[off]));
                    bfh[nf2 * 4 + 0] = r[0]; bfh[nf2 * 4 + 1] = r[1];
                    bfh[nf2 * 4 + 2] = r[2]; bfh[nf2 * 4 + 3] = r[3];
                    ldsm4t(r, smem_u32(&Bl[off]));
                    bfl[nf2 * 4 + 0] = r[0]; bfl[nf2 * 4 + 1] = r[1];
                    bfl[nf2 * 4 + 2] = r[2]; bfl[nf2 * 4 + 3] = r[3];
                }
            }
#pragma unroll
            for (int mf = 0; mf < 2; mf++)
#pragma unroll
                for (int nf = 0; nf < 8; nf++) {
                    mma16816(d[mf][nf], ah[mf], &bfh[nf * 2]);
                    mma16816(d[mf][nf], ah[mf], &bfl[nf * 2]);
                    mma16816(d[mf][nf], al[mf], &bfh[nf * 2]);
                }
        }
        __syncthreads();
    }

    /* ---- epilogue ---- */
    int ri = lane >> 2, c2 = (lane & 3) * 2;
#pragma unroll
    for (int mf = 0; mf < 2; mf++) {
#pragma unroll
        for (int nf = 0; nf < 8; nf++) {
            int col = col0 + wn * 64 + nf * 8 + c2;
#pragma unroll
            for (int hv = 0; hv < 2; hv++) {
                int row = row0 + wm * 32 + mf * 16 + ri + hv * 8;
                float v0 = d[mf][nf][hv * 2];
                float v1 = d[mf][nf][hv * 2 + 1];
                int bidx = row >> 11, sidx = row & 2047;
                if (MODE <= 1) {
                    v0 *= SCALE; v1 *= SCALE;
                    int hh = col >> 7, dh = col & 127;
                    float* dst = (MODE == 0) ? g_q : g_k;
                    float2 o = make_float2(v0, v1);
                    *(float2*)&dst[(((size_t)bidx * HH + hh) * SS + sidx) * DHH + dh] = o;
                } else if (MODE == 2) {
                    float2 o = make_float2(v0, v1);
                    *(float2*)&g_v[(((size_t)bidx * HH + hz) * SS + sidx) * DHH + col] = o;
                } else {
                    float2 o = make_float2(v0, v1);
                    *(float2*)&C[(size_t)row * 1024 + col] = o;
                }
            }
        }
    }
}

/* ------------------------------------------------------------------ */
/* Tensor-core flash attention: BQ=64, BKV=64, 256 threads             */
/* ------------------------------------------------------------------ */
#define QSTR 136
#define SSTR 65
#define PSTR 72

#define OFF_QH 0
#define OFF_QL (OFF_QH + 64 * QSTR)
#define OFF_KH (OFF_QL + 64 * QSTR)
#define OFF_KL (OFF_KH + 64 * QSTR)
#define OFF_END_BF (OFF_KL + 64 * QSTR)          /* in bf16 elems */
#define BYTES_BF (OFF_END_BF * 2)
#define OFF_S  BYTES_BF                           /* bytes */
#define BYTES_S (64 * SSTR * 4)
#define OFF_PH (OFF_S + BYTES_S)
#define OFF_PL (OFF_PH + 64 * PSTR * 2)
#define OFF_ST (OFF_PL + 64 * PSTR * 2)           /* stats: M,L,C 64 floats each */
#define ATTN_BYTES (OFF_ST + 3 * 64 * 4)

__global__ void __launch_bounds__(256) attn_tc() {
    extern __shared__ char smem[];
    __nv_bfloat16* Qh = (__nv_bfloat16*)smem + OFF_QH;
    __nv_bfloat16* Ql = (__nv_bfloat16*)smem + OFF_QL;
    __nv_bfloat16* Kh = (__nv_bfloat16*)smem + OFF_KH;
    __nv_bfloat16* Kl = (__nv_bfloat16*)smem + OFF_KL;
    float* Ssm = (float*)(smem + OFF_S);
    __nv_bfloat16* Ph = (__nv_bfloat16*)(smem + OFF_PH);
    __nv_bfloat16* Pl = (__nv_bfloat16*)(smem + OFF_PL);
    float* Ms = (float*)(smem + OFF_ST);
    float* Ls = Ms + 64;
    float* Cs = Ls + 64;

    int tid = threadIdx.x;
    int warp = tid >> 5, lane = tid & 31;
    int wm = warp & 3, wn = warp >> 2;
    int bh = blockIdx.y;
    int q0 = blockIdx.x * 64;

    const float* qbase = g_q + (size_t)bh * SS * DHH;
    const float* kbase = g_k + (size_t)bh * SS * DHH;
    const float* vbase = g_v + (size_t)bh * SS * DHH;

    /* stage Q (once) */
#pragma unroll
    for (int it = 0; it < 8; it++) {
        int idx = it * 256 + tid;
        int r = idx >> 5, c4 = (idx & 31) * 4;
        float4 x = *(const float4*)(qbase + (size_t)(q0 + r) * DHH + c4);
        uint32_t h0, l0, h1, l1;
        split_pair(x.x, x.y, h0, l0);
        split_pair(x.z, x.w, h1, l1);
        *(uint32_t*)&Qh[r * QSTR + c4] = h0;
        *(uint32_t*)&Qh[r * QSTR + c4 + 2] = h1;
        *(uint32_t*)&Ql[r * QSTR + c4] = l0;
        *(uint32_t*)&Ql[r * QSTR + c4 + 2] = l1;
    }
    if (tid < 64) { Ms[tid] = -1e30f; Ls[tid] = 0.f; }

    float oacc[8][4];
#pragma unroll
    for (int j = 0; j < 8; j++)
#pragma unroll
        for (int c = 0; c < 4; c++) oacc[j][c] = 0.f;

    __syncthreads();

    for (int kv0 = 0; kv0 < SS; kv0 += 64) {
        /* stage K */
#pragma unroll
        for (int it = 0; it < 8; it++) {
            int idx = it * 256 + tid;
            int r = idx >> 5, c4 = (idx & 31) * 4;
            float4 x = *(const float4*)(kbase + (size_t)(kv0 + r) * DHH + c4);
            uint32_t h0, l0, h1, l1;
            split_pair(x.x, x.y, h0, l0);
            split_pair(x.z, x.w, h1, l1);
            *(uint32_t*)&Kh[r * QSTR + c4] = h0;
            *(uint32_t*)&Kh[r * QSTR + c4 + 2] = h1;
            *(uint32_t*)&Kl[r * QSTR + c4] = l0;
            *(uint32_t*)&Kl[r * QSTR + c4 + 2] = l1;
        }
        __syncthreads();

        /* S = Q @ K^T : warp tile 16(M) x 32(N), K=128 */
        float sacc[4][4];
#pragma unroll
        for (int j = 0; j < 4; j++)
#pragma unroll
            for (int c = 0; c < 4; c++) sacc[j][c] = 0.f;

#pragma unroll
        for (int ks = 0; ks < 8; ks++) {
            uint32_t ah[4], al[4];
            {
                int off = (wm * 16 + (lane & 15)) * QSTR + ks * 16 + (lane >> 4) * 8;
                ldsm4(ah, smem_u32(&Qh[off]));
                ldsm4(al, smem_u32(&Ql[off]));
            }
            uint32_t bfh[8], bfl[8];
#pragma unroll
            for (int nf2 = 0; nf2 < 2; nf2++) {
                int off = (wn * 32 + nf2 * 16 + (lane & 15)) * QSTR + ks * 16 + (lane >> 4) * 8;
                uint32_t r[4];
                ldsm4(r, smem_u32(&Kh[off]));
                bfh[nf2 * 4 + 0] = r[0]; bfh[nf2 * 4 + 1] = r[2];
                bfh[nf2 * 4 + 2] = r[1]; bfh[nf2 * 4 + 3] = r[3];
                ldsm4(r, smem_u32(&Kl[off]));
                bfl[nf2 * 4 + 0] = r[0]; bfl[nf2 * 4 + 1] = r[2];
                bfl[nf2 * 4 + 2] = r[1]; bfl[nf2 * 4 + 3] = r[3];
            }
#pragma unroll
            for (int nf = 0; nf < 4; nf++) {
                mma16816(sacc[nf], ah, &bfh[nf * 2]);
                mma16816(sacc[nf], ah, &bfl[nf * 2]);
                mma16816(sacc[nf], al, &bfh[nf * 2]);
            }
        }

        /* write S to smem */
        {
            int ri = lane >> 2, c2 = (lane & 3) * 2;
#pragma unroll
            for (int nf = 0; nf < 4; nf++) {
                int col = wn * 32 + nf * 8 + c2;
                int row = wm * 16 + ri;
                Ssm[row * SSTR + col] = sacc[nf][0];
                Ssm[row * SSTR + col + 1] = sacc[nf][1];
                Ssm[(row + 8) * SSTR + col] = sacc[nf][2];
                Ssm[(row + 8) * SSTR + col + 1] = sacc[nf][3];
            }
        }
        __syncthreads();

        /* online softmax: 4 threads per row */
        {
            int row = tid >> 2, seg = tid & 3;
            float mloc = -1e30f;
#pragma unroll 4
            for (int c = seg * 16; c < seg * 16 + 16; c++)
                mloc = fmaxf(mloc, Ssm[row * SSTR + c]);
            mloc = fmaxf(mloc, __shfl_xor_sync(0xffffffffu, mloc, 1));
            mloc = fmaxf(mloc, __shfl_xor_sync(0xffffffffu, mloc, 2));
            float mold = Ms[row];
            float mnew = fmaxf(mold, mloc);
            float lsum = 0.f;
#pragma unroll 4
            for (int c = seg * 16; c < seg * 16 + 16; c++) {
                float p = __expf(Ssm[row * SSTR + c] - mnew);
                Ssm[row * SSTR + c] = p;
                lsum += p;
            }
            lsum += __shfl_xor_sync(0xffffffffu, lsum, 1);
            lsum += __shfl_xor_sync(0xffffffffu, lsum, 2);
            if (seg == 0) {
                float corr = __expf(mold - mnew);
                Ms[row] = mnew;
                Cs[row] = corr;
                Ls[row] = Ls[row] * corr + lsum;
            }
        }

        /* stage V into K buffers (K-frag reads finished before last sync) */
#pragma unroll
        for (int it = 0; it < 8; it++) {
            int idx = it * 256 + tid;
            int r = idx >> 5, c4 = (idx & 31) * 4;
            float4 x = *(const float4*)(vbase + (size_t)(kv0 + r) * DHH + c4);
            uint32_t h0, l0, h1, l1;
            split_pair(x.x, x.y, h0, l0);
            split_pair(x.z, x.w, h1, l1);
            *(uint32_t*)&Kh[r * QSTR + c4] = h0;
            *(uint32_t*)&Kh[r * QSTR + c4 + 2] = h1;
            *(uint32_t*)&Kl[r * QSTR + c4] = l0;
            *(uint32_t*)&Kl[r * QSTR + c4 + 2] = l1;
        }
        __syncthreads();

        /* convert P -> bf16 hi/lo */
#pragma unroll
        for (int it = 0; it < 8; it++) {
            int idx2 = it * 256 + tid;
            int r = idx2 >> 5;
            int cc = (idx2 & 31) * 2;
            float p0 = Ssm[r * SSTR + cc];
            float p1 = Ssm[r * SSTR + cc + 1];
            uint32_t h0, l0;
            split_pair(p0, p1, h0, l0);
            *(uint32_t*)&Ph[r * PSTR + cc] = h0;
            *(uint32_t*)&Pl[r * PSTR + cc] = l0;
        }
        __syncthreads();

        /* rescale O acc */
        {
            int ri = lane >> 2;
            float c0 = Cs[wm * 16 + ri];
            float c1 = Cs[wm * 16 + ri + 8];
#pragma unroll
            for (int nf = 0; nf < 8; nf++) {
                oacc[nf][0] *= c0; oacc[nf][1] *= c0;
                oacc[nf][2] *= c1; oacc[nf][3] *= c1;
            }
        }

        /* O += P @ V : warp tile 16(M) x 64(N), K=64 */
#pragma unroll
        for (int ks = 0; ks < 4; ks++) {
            uint32_t ah[4], al[4];
            {
                int off = (wm * 16 + (lane & 15)) * PSTR + ks * 16 + (lane >> 4) * 8;
                ldsm4(ah, smem_u32(&Ph[off]));
                ldsm4(al, smem_u32(&Pl[off]));
            }
            uint32_t bfh[16], bfl[16];
#pragma unroll
            for (int nf2 = 0; nf2 < 4; nf2++) {
                int off = (ks * 16 + (lane & 15)) * QSTR + wn * 64 + nf2 * 16 + (lane >> 4) * 8;
                uint32_t r[4];
                ldsm4t(r, smem_u32(&Kh[off]));
                bfh[nf2 * 4 + 0] = r[0]; bfh[nf2 * 4 + 1] = r[1];
                bfh[nf2 * 4 + 2] = r[2]; bfh[nf2 * 4 + 3] = r[3];
                ldsm4t(r, smem_u32(&Kl[off]));
                bfl[nf2 * 4 + 0] = r[0]; bfl[nf2 * 4 + 1] = r[1];
                bfl[nf2 * 4 + 2] = r[2]; bfl[nf2 * 4 + 3] = r[3];
            }
#pragma unroll
            for (int nf = 0; nf < 8; nf++) {
                mma16816(oacc[nf], ah, &bfh[nf * 2]);
                mma16816(oacc[nf], ah, &bfl[nf * 2]);
                mma16816(oacc[nf], al, &bfh[nf * 2]);
            }
        }
        __syncthreads();
    }

    /* epilogue: normalize + store g_res[t, h*128+dh] */
    {
        int b = bh >> 3;
        int h2 = bh & 7;
        int ri = lane >> 2;
        int cc = (lane & 3) * 2;
        float li0 = 1.f / Ls[wm * 16 + ri];
        float li1 = 1.f / Ls[wm * 16 + ri + 8];
#pragma unroll
        for (int nf = 0; nf < 8; nf++) {
            int col = wn * 64 + nf * 8 + cc;
            size_t t0 = (size_t)b * SS + q0 + wm * 16 + ri;
            float2 o0 = make_float2(oacc[nf][0] * li0, oacc[nf][1] * li0);
            float2 o1 = make_float2(oacc[nf][2] * li1, oacc[nf][3] * li1);
            *(float2*)&g_res[t0 * 1024 + h2 * 128 + col] = o0;
            *(float2*)&g_res[(t0 + 8) * 1024 + h2 * 128 + col] = o1;
        }
    }
}

/* ------------------------------------------------------------------ */
extern "C" void kernel_launch(void* const* d_in, const int* in_sizes, int n_in,
                              void* d_out, int out_size) {
    (void)in_sizes; (void)n_in; (void)out_size;
    const float* q_src = (const float*)d_in[0];
    const float* k_src = (const float*)d_in[1];
    const float* v_src = (const float*)d_in[2];
    const float* Wq    = (const float*)d_in[3];
    const float* Wk    = (const float*)d_in[4];
    const float* Wv    = (const float*)d_in[5];
    const float* Wo    = (const float*)d_in[6];
    const float* sel_v = (const float*)d_in[7];
    const float* sel_o = (const float*)d_in[8];
    float* out = (float*)d_out;

    cudaFuncSetAttribute(attn_tc,
                         cudaFuncAttributeMaxDynamicSharedMemorySize,
                         ATTN_BYTES);

    gates_kernel<<<dim3(TOK / 8, 2), 256>>>(k_src, sel_v, q_src, sel_o);
    tc_gemm<0><<<dim3(8, 32), 256>>>(q_src, Wq, nullptr);
    tc_gemm<1><<<dim3(8, 32), 256>>>(k_src, Wk, nullptr);
    tc_gemm<2><<<dim3(1, 32, 8), 256>>>(v_src, Wv, nullptr);
    attn_tc<<<dim3(SS / 64, BB * HH), 256, ATTN_BYTES>>>();
    tc_gemm<3><<<dim3(8, 32), 256>>>(nullptr, Wo, out);
}

// round 7
// speedup vs baseline: 2.2885x; 1.0594x over previous
#include <cuda_runtime.h>
#include <cuda_bf16.h>
#include <cstdint>
#include <math.h>

#define BB   2
#define SS   2048
#define DD   1024
#define HH   8
#define EE   4
#define DHH  128
#define TOK  (BB*SS)
#define SCALE 0.29730177875068026f      /* 128^-0.25 */

/* ------------------------------------------------------------------ */
/* scratch                                                             */
/* ------------------------------------------------------------------ */
__device__ float g_q[TOK * DD];        /* [b,h,s,dh] */
__device__ float g_k[TOK * DD];
__device__ float g_v[TOK * DD];
__device__ float g_res[TOK * DD];      /* [t, h*128+dh] */
__device__ float g_gv[TOK * HH * EE];
__device__ float g_go[TOK * HH * EE];

/* ------------------------------------------------------------------ */
/* helpers                                                             */
/* ------------------------------------------------------------------ */
__device__ __forceinline__ uint32_t smem_u32(const void* p) {
    return (uint32_t)__cvta_generic_to_shared(p);
}
__device__ __forceinline__ void ldsm4(uint32_t* r, uint32_t a) {
    asm volatile("ldmatrix.sync.aligned.m8n8.x4.shared.b16 {%0,%1,%2,%3}, [%4];"
                 : "=r"(r[0]), "=r"(r[1]), "=r"(r[2]), "=r"(r[3]) : "r"(a));
}
__device__ __forceinline__ void ldsm4t(uint32_t* r, uint32_t a) {
    asm volatile("ldmatrix.sync.aligned.m8n8.x4.trans.shared.b16 {%0,%1,%2,%3}, [%4];"
                 : "=r"(r[0]), "=r"(r[1]), "=r"(r[2]), "=r"(r[3]) : "r"(a));
}
__device__ __forceinline__ void mma16816(float* d, const uint32_t* a, const uint32_t* b) {
    asm volatile(
        "mma.sync.aligned.m16n8k16.row.col.f32.bf16.bf16.f32 "
        "{%0,%1,%2,%3}, {%4,%5,%6,%7}, {%8,%9}, {%0,%1,%2,%3};"
        : "+f"(d[0]), "+f"(d[1]), "+f"(d[2]), "+f"(d[3])
        : "r"(a[0]), "r"(a[1]), "r"(a[2]), "r"(a[3]), "r"(b[0]), "r"(b[1]));
}
__device__ __forceinline__ uint32_t packbf(float x, float y) {
    __nv_bfloat162 t = __floats2bfloat162_rn(x, y);
    return *reinterpret_cast<uint32_t*>(&t);
}
__device__ __forceinline__ void split_pair(float x, float y, uint32_t& h, uint32_t& l) {
    float hx = __bfloat162float(__float2bfloat16(x));
    float hy = __bfloat162float(__float2bfloat16(y));
    h = packbf(hx, hy);
    l = packbf(x - hx, y - hy);
}

/* ------------------------------------------------------------------ */
/* Gates                                                               */
/* ------------------------------------------------------------------ */
__global__ void gates_kernel(const float* __restrict__ k_src,
                             const float* __restrict__ sel_v,
                             const float* __restrict__ q_src,
                             const float* __restrict__ sel_o) {
    int w = threadIdx.x >> 5;
    int lane = threadIdx.x & 31;
    int t = blockIdx.x * 8 + w;

    const float* x; const float* sel; float* out;
    if (blockIdx.y == 0) { x = k_src; sel = sel_v; out = g_gv; }
    else                 { x = q_src; sel = sel_o; out = g_go; }

    const float4* xr = (const float4*)(x + (size_t)t * DD);
    const float4* sr = (const float4*)(sel + (size_t)lane * DD);
    float acc = 0.f;
#pragma unroll 8
    for (int i = 0; i < DD / 4; i++) {
        float4 a = xr[i], b = sr[i];
        acc += a.x * b.x + a.y * b.y + a.z * b.z + a.w * b.w;
    }
    float g = 1.f / (1.f + __expf(-acc));

    __shared__ float sh[8][32];
    sh[w][lane] = g;
    __syncwarp();

    if (lane < HH) {
        float vv[4];
#pragma unroll
        for (int e = 0; e < 4; e++) vv[e] = sh[w][lane * 4 + e];
        int i1 = 0; float m1 = vv[0];
#pragma unroll
        for (int e = 1; e < 4; e++) if (vv[e] > m1) { m1 = vv[e]; i1 = e; }
        int i2 = -1; float m2 = -1e30f;
#pragma unroll
        for (int e = 0; e < 4; e++) if (e != i1 && vv[e] > m2) { m2 = vv[e]; i2 = e; }
#pragma unroll
        for (int e = 0; e < 4; e++)
            out[(size_t)t * 32 + lane * 4 + e] = (e == i1 || e == i2) ? vv[e] : 0.f;
    }
}

/* ------------------------------------------------------------------ */
/* Tensor-core GEMM (mma.sync), block 128x128, Kc=32, split bf16.      */
/* MODE 0: Q proj, 1: K proj, 2: V expert build, 3: O expert build     */
/* ------------------------------------------------------------------ */
#define ASTR 40
#define BSTR 136

template <int MODE>
__global__ void __launch_bounds__(256)
tc_gemm(const float* __restrict__ A,
        const float* __restrict__ Bm,
        float* __restrict__ C) {
    constexpr int KT = (MODE <= 1) ? 1024 : 4096;

    __shared__ __nv_bfloat16 Ah[128 * ASTR];
    __shared__ __nv_bfloat16 Al[128 * ASTR];
    __shared__ __nv_bfloat16 Bh[128 * ASTR];
    __shared__ __nv_bfloat16 Bl[128 * ASTR];

    int tid = threadIdx.x;
    int warp = tid >> 5, lane = tid & 31;
    int wm = warp & 3, wn = warp >> 2;
    int row0 = blockIdx.y * 128;
    int col0 = blockIdx.x * 128;
    int hz = blockIdx.z;

    const float* gates = (MODE == 2) ? g_gv : g_go;
    const float* Bp = Bm;
    if (MODE == 2) Bp = Bm + (size_t)hz * (EE * DD * DHH);

    float d[2][8][4];
#pragma unroll
    for (int i = 0; i < 2; i++)
#pragma unroll
        for (int j = 0; j < 8; j++)
#pragma unroll
            for (int c = 0; c < 4; c++) d[i][j][c] = 0.f;

    for (int k0 = 0; k0 < KT; k0 += 32) {
#pragma unroll
        for (int it = 0; it < 4; it++) {
            int idx = it * 256 + tid;
            int r = idx >> 3, c4 = (idx & 7) * 4;
            int kg = k0 + c4;
            int rt = row0 + r;
            const float* src;
            float gm = 1.f;
            if (MODE <= 1) {
                src = A + (size_t)rt * 1024 + kg;
            } else if (MODE == 2) {
                src = A + (size_t)rt * 1024 + (kg & 1023);
                gm = gates[(size_t)rt * 32 + hz * 4 + (kg >> 10)];
            } else {
                int hh = kg >> 9, e = (kg >> 7) & 3, dh = kg & 127;
                src = g_res + (size_t)rt * 1024 + hh * 128 + dh;
                gm = gates[(size_t)rt * 32 + hh * 4 + e];
            }
            float4 x = *(const float4*)src;
            x.x *= gm; x.y *= gm; x.z *= gm; x.w *= gm;
            uint32_t h0, l0, h1, l1;
            split_pair(x.x, x.y, h0, l0);
            split_pair(x.z, x.w, h1, l1);
            *(uint32_t*)&Ah[r * ASTR + c4] = h0;
            *(uint32_t*)&Ah[r * ASTR + c4 + 2] = h1;
            *(uint32_t*)&Al[r * ASTR + c4] = l0;
            *(uint32_t*)&Al[r * ASTR + c4 + 2] = l1;
        }
        if (MODE <= 1) {
#pragma unroll
            for (int it = 0; it < 4; it++) {
                int idx = it * 256 + tid;
                int r = idx >> 3, c4 = (idx & 7) * 4;
                float4 x = *(const float4*)(Bp + (size_t)(col0 + r) * 1024 + k0 + c4);
                uint32_t h0, l0, h1, l1;
                split_pair(x.x, x.y, h0, l0);
                split_pair(x.z, x.w, h1, l1);
                *(uint32_t*)&Bh[r * ASTR + c4] = h0;
                *(uint32_t*)&Bh[r * ASTR + c4 + 2] = h1;
                *(uint32_t*)&Bl[r * ASTR + c4] = l0;
                *(uint32_t*)&Bl[r * ASTR + c4 + 2] = l1;
            }
        } else {
            constexpr int NLD = (MODE == 2) ? 128 : 1024;
#pragma unroll
            for (int it = 0; it < 4; it++) {
                int idx = it * 256 + tid;
                int kr = idx >> 5, nc = (idx & 31) * 4;
                float4 x = *(const float4*)(Bp + (size_t)(k0 + kr) * NLD + col0 + nc);
                uint32_t h0, l0, h1, l1;
                split_pair(x.x, x.y, h0, l0);
                split_pair(x.z, x.w, h1, l1);
                *(uint32_t*)&Bh[kr * BSTR + nc] = h0;
                *(uint32_t*)&Bh[kr * BSTR + nc + 2] = h1;
                *(uint32_t*)&Bl[kr * BSTR + nc] = l0;
                *(uint32_t*)&Bl[kr * BSTR + nc + 2] = l1;
            }
        }
        __syncthreads();

#pragma unroll
        for (int ks = 0; ks < 2; ks++) {
            uint32_t ah[2][4], al[2][4];
#pragma unroll
            for (int mf = 0; mf < 2; mf++) {
                int off = (wm * 32 + mf * 16 + (lane & 15)) * ASTR + ks * 16 + (lane >> 4) * 8;
                ldsm4(ah[mf], smem_u32(&Ah[off]));
                ldsm4(al[mf], smem_u32(&Al[off]));
            }
            uint32_t bfh[16], bfl[16];
            if (MODE <= 1) {
#pragma unroll
                for (int nf2 = 0; nf2 < 4; nf2++) {
                    int off = (wn * 64 + nf2 * 16 + (lane & 15)) * ASTR + ks * 16 + (lane >> 4) * 8;
                    uint32_t r[4];
                    ldsm4(r, smem_u32(&Bh[off]));
                    bfh[nf2 * 4 + 0] = r[0]; bfh[nf2 * 4 + 1] = r[2];
                    bfh[nf2 * 4 + 2] = r[1]; bfh[nf2 * 4 + 3] = r[3];
                    ldsm4(r, smem_u32(&Bl[off]));
                    bfl[nf2 * 4 + 0] = r[0]; bfl[nf2 * 4 + 1] = r[2];
                    bfl[nf2 * 4 + 2] = r[1]; bfl[nf2 * 4 + 3] = r[3];
                }
            } else {
#pragma unroll
                for (int nf2 = 0; nf2 < 4; nf2++) {
                    int off = (ks * 16 + (lane & 15)) * BSTR + wn * 64 + nf2 * 16 + (lane >> 4) * 8;
                    uint32_t r[4];
                    ldsm4t(r, smem_u32(&Bh[off]));
                    bfh[nf2 * 4 + 0] = r[0]; bfh[nf2 * 4 + 1] = r[1];
                    bfh[nf2 * 4 + 2] = r[2]; bfh[nf2 * 4 + 3] = r[3];
                    ldsm4t(r, smem_u32(&Bl[off]));
                    bfl[nf2 * 4 + 0] = r[0]; bfl[nf2 * 4 + 1] = r[1];
                    bfl[nf2 * 4 + 2] = r[2]; bfl[nf2 * 4 + 3] = r[3];
                }
            }
#pragma unroll
            for (int mf = 0; mf < 2; mf++)
#pragma unroll
                for (int nf = 0; nf < 8; nf++) {
                    mma16816(d[mf][nf], ah[mf], &bfh[nf * 2]);
                    mma16816(d[mf][nf], ah[mf], &bfl[nf * 2]);
                    mma16816(d[mf][nf], al[mf], &bfh[nf * 2]);
                }
        }
        __syncthreads();
    }

    int ri = lane >> 2, c2 = (lane & 3) * 2;
#pragma unroll
    for (int mf = 0; mf < 2; mf++) {
#pragma unroll
        for (int nf = 0; nf < 8; nf++) {
            int col = col0 + wn * 64 + nf * 8 + c2;
#pragma unroll
            for (int hv = 0; hv < 2; hv++) {
                int row = row0 + wm * 32 + mf * 16 + ri + hv * 8;
                float v0 = d[mf][nf][hv * 2];
                float v1 = d[mf][nf][hv * 2 + 1];
                int bidx = row >> 11, sidx = row & 2047;
                if (MODE <= 1) {
                    v0 *= SCALE; v1 *= SCALE;
                    int hh = col >> 7, dh = col & 127;
                    float* dst = (MODE == 0) ? g_q : g_k;
                    float2 o = make_float2(v0, v1);
                    *(float2*)&dst[(((size_t)bidx * HH + hh) * SS + sidx) * DHH + dh] = o;
                } else if (MODE == 2) {
                    float2 o = make_float2(v0, v1);
                    *(float2*)&g_v[(((size_t)bidx * HH + hz) * SS + sidx) * DHH + col] = o;
                } else {
                    float2 o = make_float2(v0, v1);
                    *(float2*)&C[(size_t)row * 1024 + col] = o;
                }
            }
        }
    }
}

/* ------------------------------------------------------------------ */
/* FA2-style attention: BQ=128, BKV=64, 8 warps, register softmax.     */
/* ------------------------------------------------------------------ */
#define QS 136
#define A_OFF_QH 0
#define A_OFF_QL (A_OFF_QH + 128 * QS)
#define A_OFF_KH (A_OFF_QL + 128 * QS)
#define A_OFF_KL (A_OFF_KH + 64 * QS)
#define A_OFF_VH (A_OFF_KL + 64 * QS)
#define A_OFF_VL (A_OFF_VH + 64 * QS)
#define A_ELEMS  (A_OFF_VL + 64 * QS)
#define ATTN_BYTES (A_ELEMS * 2)

__global__ void __launch_bounds__(256, 1) attn_fa() {
    extern __shared__ __nv_bfloat16 sm[];
    __nv_bfloat16* Qh = sm + A_OFF_QH;
    __nv_bfloat16* Ql = sm + A_OFF_QL;
    __nv_bfloat16* Kh = sm + A_OFF_KH;
    __nv_bfloat16* Kl = sm + A_OFF_KL;
    __nv_bfloat16* Vh = sm + A_OFF_VH;
    __nv_bfloat16* Vl = sm + A_OFF_VL;

    int tid = threadIdx.x;
    int warp = tid >> 5, lane = tid & 31;
    int bh = blockIdx.y;
    int q0 = blockIdx.x * 128;

    const float* qbase = g_q + (size_t)bh * SS * DHH;
    const float* kbase = g_k + (size_t)bh * SS * DHH;
    const float* vbase = g_v + (size_t)bh * SS * DHH;

    /* stage Q hi/lo once: 128 rows x 128 cols */
#pragma unroll
    for (int it = 0; it < 16; it++) {
        int idx = it * 256 + tid;
        int r = idx >> 5, c4 = (idx & 31) * 4;
        float4 x = *(const float4*)(qbase + (size_t)(q0 + r) * DHH + c4);
        uint32_t h0, l0, h1, l1;
        split_pair(x.x, x.y, h0, l0);
        split_pair(x.z, x.w, h1, l1);
        *(uint32_t*)&Qh[r * QS + c4] = h0;
        *(uint32_t*)&Qh[r * QS + c4 + 2] = h1;
        *(uint32_t*)&Ql[r * QS + c4] = l0;
        *(uint32_t*)&Ql[r * QS + c4 + 2] = l1;
    }

    float oacc[16][4];
#pragma unroll
    for (int j = 0; j < 16; j++)
#pragma unroll
        for (int c = 0; c < 4; c++) oacc[j][c] = 0.f;
    float mold[2] = { -1e30f, -1e30f };
    float lsum[2] = { 0.f, 0.f };

    __syncthreads();

    for (int kv0 = 0; kv0 < SS; kv0 += 64) {
        /* stage K and V hi/lo: 64 x 128 each */
#pragma unroll
        for (int it = 0; it < 8; it++) {
            int idx = it * 256 + tid;
            int r = idx >> 5, c4 = (idx & 31) * 4;
            float4 x = *(const float4*)(kbase + (size_t)(kv0 + r) * DHH + c4);
            uint32_t h0, l0, h1, l1;
            split_pair(x.x, x.y, h0, l0);
            split_pair(x.z, x.w, h1, l1);
            *(uint32_t*)&Kh[r * QS + c4] = h0;
            *(uint32_t*)&Kh[r * QS + c4 + 2] = h1;
            *(uint32_t*)&Kl[r * QS + c4] = l0;
            *(uint32_t*)&Kl[r * QS + c4 + 2] = l1;
            float4 y = *(const float4*)(vbase + (size_t)(kv0 + r) * DHH + c4);
            split_pair(y.x, y.y, h0, l0);
            split_pair(y.z, y.w, h1, l1);
            *(uint32_t*)&Vh[r * QS + c4] = h0;
            *(uint32_t*)&Vh[r * QS + c4 + 2] = h1;
            *(uint32_t*)&Vl[r * QS + c4] = l0;
            *(uint32_t*)&Vl[r * QS + c4 + 2] = l1;
        }
        __syncthreads();

        /* S = Q K^T : warp tile 16(M) x 64(N), K=128 */
        float sacc[8][4];
#pragma unroll
        for (int j = 0; j < 8; j++)
#pragma unroll
            for (int c = 0; c < 4; c++) sacc[j][c] = 0.f;

#pragma unroll
        for (int ks = 0; ks < 8; ks++) {
            uint32_t ah[4], al[4];
            {
                int off = (warp * 16 + (lane & 15)) * QS + ks * 16 + (lane >> 4) * 8;
                ldsm4(ah, smem_u32(&Qh[off]));
                ldsm4(al, smem_u32(&Ql[off]));
            }
#pragma unroll
            for (int ng = 0; ng < 4; ng++) {
                int off = (ng * 16 + (lane & 15)) * QS + ks * 16 + (lane >> 4) * 8;
                uint32_t rh[4], rl[4];
                ldsm4(rh, smem_u32(&Kh[off]));
                ldsm4(rl, smem_u32(&Kl[off]));
                /* non-trans x4: r0=n0-7/k0-7, r1=n8-15/k0-7, r2=n0-7/k8-15, r3=n8-15/k8-15 */
                uint32_t b0h[2] = { rh[0], rh[2] }, b1h[2] = { rh[1], rh[3] };
                uint32_t b0l[2] = { rl[0], rl[2] }, b1l[2] = { rl[1], rl[3] };
                mma16816(sacc[ng * 2], ah, b0h);
                mma16816(sacc[ng * 2], ah, b0l);
                mma16816(sacc[ng * 2], al, b0h);
                mma16816(sacc[ng * 2 + 1], ah, b1h);
                mma16816(sacc[ng * 2 + 1], ah, b1l);
                mma16816(sacc[ng * 2 + 1], al, b1h);
            }
        }

        /* register softmax: rows ri (half 0) and ri+8 (half 1) */
        float corr[2];
#pragma unroll
        for (int hf = 0; hf < 2; hf++) {
            float mx = -1e30f;
#pragma unroll
            for (int nf = 0; nf < 8; nf++) {
                mx = fmaxf(mx, sacc[nf][hf * 2]);
                mx = fmaxf(mx, sacc[nf][hf * 2 + 1]);
            }
            mx = fmaxf(mx, __shfl_xor_sync(0xffffffffu, mx, 1));
            mx = fmaxf(mx, __shfl_xor_sync(0xffffffffu, mx, 2));
            float mnew = fmaxf(mold[hf], mx);
            corr[hf] = __expf(mold[hf] - mnew);
            mold[hf] = mnew;
            float ls = 0.f;
#pragma unroll
            for (int nf = 0; nf < 8; nf++) {
                float p0 = __expf(sacc[nf][hf * 2] - mnew);
                float p1 = __expf(sacc[nf][hf * 2 + 1] - mnew);
                sacc[nf][hf * 2] = p0;
                sacc[nf][hf * 2 + 1] = p1;
                ls += p0 + p1;
            }
            ls += __shfl_xor_sync(0xffffffffu, ls, 1);
            ls += __shfl_xor_sync(0xffffffffu, ls, 2);
            lsum[hf] = lsum[hf] * corr[hf] + ls;
        }
#pragma unroll
        for (int nf = 0; nf < 16; nf++) {
            oacc[nf][0] *= corr[0]; oacc[nf][1] *= corr[0];
            oacc[nf][2] *= corr[1]; oacc[nf][3] *= corr[1];
        }

        /* O += P V : P frags built in registers from sacc */
#pragma unroll
        for (int kk = 0; kk < 4; kk++) {
            uint32_t ph[4], pl[4];
            split_pair(sacc[kk * 2][0],     sacc[kk * 2][1],     ph[0], pl[0]);
            split_pair(sacc[kk * 2][2],     sacc[kk * 2][3],     ph[1], pl[1]);
            split_pair(sacc[kk * 2 + 1][0], sacc[kk * 2 + 1][1], ph[2], pl[2]);
            split_pair(sacc[kk * 2 + 1][2], sacc[kk * 2 + 1][3], ph[3], pl[3]);
#pragma unroll
            for (int ng = 0; ng < 8; ng++) {
                int off = (kk * 16 + (lane & 15)) * QS + ng * 16 + (lane >> 4) * 8;
                uint32_t rh[4], rl[4];
                ldsm4t(rh, smem_u32(&Vh[off]));
                ldsm4t(rl, smem_u32(&Vl[off]));
                /* trans x4: b(n0-7) = {r0,r1}, b(n8-15) = {r2,r3} */
                uint32_t b0h[2] = { rh[0], rh[1] }, b1h[2] = { rh[2], rh[3] };
                uint32_t b0l[2] = { rl[0], rl[1] }, b1l[2] = { rl[2], rl[3] };
                mma16816(oacc[ng * 2], ph, b0h);
                mma16816(oacc[ng * 2], ph, b0l);
                mma16816(oacc[ng * 2], pl, b0h);
                mma16816(oacc[ng * 2 + 1], ph, b1h);
                mma16816(oacc[ng * 2 + 1], ph, b1l);
                mma16816(oacc[ng * 2 + 1], pl, b1h);
            }
        }
        __syncthreads();
    }

    /* epilogue: normalize, store g_res[t, h*128+dh] */
    {
        int b = bh >> 3;
        int h2 = bh & 7;
        int ri = lane >> 2;
        int cc = (lane & 3) * 2;
        float li0 = 1.f / lsum[0];
        float li1 = 1.f / lsum[1];
        size_t t0 = (size_t)b * SS + q0 + warp * 16 + ri;
#pragma unroll
        for (int nf = 0; nf < 16; nf++) {
            int col = nf * 8 + cc;
            float2 o0 = make_float2(oacc[nf][0] * li0, oacc[nf][1] * li0);
            float2 o1 = make_float2(oacc[nf][2] * li1, oacc[nf][3] * li1);
            *(float2*)&g_res[t0 * 1024 + h2 * 128 + col] = o0;
            *(float2*)&g_res[(t0 + 8) * 1024 + h2 * 128 + col] = o1;
        }
    }
}

/* ------------------------------------------------------------------ */
extern "C" void kernel_launch(void* const* d_in, const int* in_sizes, int n_in,
                              void* d_out, int out_size) {
    (void)in_sizes; (void)n_in; (void)out_size;
    const float* q_src = (const float*)d_in[0];
    const float* k_src = (const float*)d_in[1];
    const float* v_src = (const float*)d_in[2];
    const float* Wq    = (const float*)d_in[3];
    const float* Wk    = (const float*)d_in[4];
    const float* Wv    = (const float*)d_in[5];
    const float* Wo    = (const float*)d_in[6];
    const float* sel_v = (const float*)d_in[7];
    const float* sel_o = (const float*)d_in[8];
    float* out = (float*)d_out;

    cudaFuncSetAttribute(attn_fa, cudaFuncAttributeMaxDynamicSharedMemorySize, ATTN_BYTES);

    gates_kernel<<<dim3(TOK / 8, 2), 256>>>(k_src, sel_v, q_src, sel_o);
    tc_gemm<0><<<dim3(8, 32), 256>>>(q_src, Wq, nullptr);
    tc_gemm<1><<<dim3(8, 32), 256>>>(k_src, Wk, nullptr);
    tc_gemm<2><<<dim3(1, 32, 8), 256>>>(v_src, Wv, nullptr);
    attn_fa<<<dim3(SS / 128, BB * HH), 256, ATTN_BYTES>>>();
    tc_gemm<3><<<dim3(8, 32), 256>>>(nullptr, Wo, out);
}

// round 8
// speedup vs baseline: 2.4691x; 1.0789x over previous
#include <cuda_runtime.h>
#include <cuda_bf16.h>
#include <cstdint>
#include <math.h>

#define BB   2
#define SS   2048
#define DD   1024
#define HH   8
#define EE   4
#define DHH  128
#define TOK  (BB*SS)
#define SCALE 0.29730177875068026f      /* 128^-0.25 */

/* ------------------------------------------------------------------ */
/* scratch (device globals)                                            */
/* ------------------------------------------------------------------ */
__device__ float g_res[TOK * DD];      /* [t, h*128+dh] */
__device__ float g_gv[TOK * HH * EE];
__device__ float g_go[TOK * HH * EE];

/* pre-split activations: [b,h,s,dh] layout */
__device__ __nv_bfloat16 g_qh[TOK * DD], g_ql[TOK * DD];
__device__ __nv_bfloat16 g_kh[TOK * DD], g_kl[TOK * DD];
__device__ __nv_bfloat16 g_vh[TOK * DD], g_vl[TOK * DD];

/* pre-split weights */
__device__ __nv_bfloat16 g_wqh[DD * DD], g_wql[DD * DD];
__device__ __nv_bfloat16 g_wkh[DD * DD], g_wkl[DD * DD];
__device__ __nv_bfloat16 g_wvh[HH * EE * DD * DHH], g_wvl[HH * EE * DD * DHH];
__device__ __nv_bfloat16 g_woh[HH * EE * DHH * DD], g_wol[HH * EE * DHH * DD];

/* ------------------------------------------------------------------ */
/* helpers                                                             */
/* ------------------------------------------------------------------ */
__device__ __forceinline__ uint32_t smem_u32(const void* p) {
    return (uint32_t)__cvta_generic_to_shared(p);
}
__device__ __forceinline__ void ldsm4(uint32_t* r, uint32_t a) {
    asm volatile("ldmatrix.sync.aligned.m8n8.x4.shared.b16 {%0,%1,%2,%3}, [%4];"
                 : "=r"(r[0]), "=r"(r[1]), "=r"(r[2]), "=r"(r[3]) : "r"(a));
}
__device__ __forceinline__ void ldsm4t(uint32_t* r, uint32_t a) {
    asm volatile("ldmatrix.sync.aligned.m8n8.x4.trans.shared.b16 {%0,%1,%2,%3}, [%4];"
                 : "=r"(r[0]), "=r"(r[1]), "=r"(r[2]), "=r"(r[3]) : "r"(a));
}
__device__ __forceinline__ void mma16816(float* d, const uint32_t* a, const uint32_t* b) {
    asm volatile(
        "mma.sync.aligned.m16n8k16.row.col.f32.bf16.bf16.f32 "
        "{%0,%1,%2,%3}, {%4,%5,%6,%7}, {%8,%9}, {%0,%1,%2,%3};"
        : "+f"(d[0]), "+f"(d[1]), "+f"(d[2]), "+f"(d[3])
        : "r"(a[0]), "r"(a[1]), "r"(a[2]), "r"(a[3]), "r"(b[0]), "r"(b[1]));
}
__device__ __forceinline__ uint32_t packbf(float x, float y) {
    __nv_bfloat162 t = __floats2bfloat162_rn(x, y);
    return *reinterpret_cast<uint32_t*>(&t);
}
__device__ __forceinline__ void split_pair(float x, float y, uint32_t& h, uint32_t& l) {
    float hx = __bfloat162float(__float2bfloat16(x));
    float hy = __bfloat162float(__float2bfloat16(y));
    h = packbf(hx, hy);
    l = packbf(x - hx, y - hy);
}
__device__ __forceinline__ void cpa16(uint32_t dst, const void* src) {
    asm volatile("cp.async.cg.shared.global [%0], [%1], 16;" :: "r"(dst), "l"(src));
}
#define CP_COMMIT() asm volatile("cp.async.commit_group;" ::: "memory")
#define CP_WAIT0()  asm volatile("cp.async.wait_group 0;" ::: "memory")
#define CP_WAIT1()  asm volatile("cp.async.wait_group 1;" ::: "memory")

/* ------------------------------------------------------------------ */
/* Weight pre-split: fp32 -> bf16 hi/lo                                */
/* ------------------------------------------------------------------ */
template <int W>
__global__ void wsplit(const float4* __restrict__ src, int n4) {
    int i = blockIdx.x * 256 + threadIdx.x;
    if (i >= n4) return;
    float4 x = src[i];
    uint32_t h0, l0, h1, l1;
    split_pair(x.x, x.y, h0, l0);
    split_pair(x.z, x.w, h1, l1);
    uint2* dh; uint2* dl;
    if (W == 0)      { dh = (uint2*)g_wqh; dl = (uint2*)g_wql; }
    else if (W == 1) { dh = (uint2*)g_wkh; dl = (uint2*)g_wkl; }
    else if (W == 2) { dh = (uint2*)g_wvh; dl = (uint2*)g_wvl; }
    else             { dh = (uint2*)g_woh; dl = (uint2*)g_wol; }
    dh[i] = make_uint2(h0, h1);
    dl[i] = make_uint2(l0, l1);
}

/* ------------------------------------------------------------------ */
/* Gates                                                               */
/* ------------------------------------------------------------------ */
__global__ void gates_kernel(const float* __restrict__ k_src,
                             const float* __restrict__ sel_v,
                             const float* __restrict__ q_src,
                             const float* __restrict__ sel_o) {
    int w = threadIdx.x >> 5;
    int lane = threadIdx.x & 31;
    int t = blockIdx.x * 8 + w;

    const float* x; const float* sel; float* out;
    if (blockIdx.y == 0) { x = k_src; sel = sel_v; out = g_gv; }
    else                 { x = q_src; sel = sel_o; out = g_go; }

    const float4* xr = (const float4*)(x + (size_t)t * DD);
    const float4* sr = (const float4*)(sel + (size_t)lane * DD);
    float acc = 0.f;
#pragma unroll 8
    for (int i = 0; i < DD / 4; i++) {
        float4 a = xr[i], b = sr[i];
        acc += a.x * b.x + a.y * b.y + a.z * b.z + a.w * b.w;
    }
    float g = 1.f / (1.f + __expf(-acc));

    __shared__ float sh[8][32];
    sh[w][lane] = g;
    __syncwarp();

    if (lane < HH) {
        float vv[4];
#pragma unroll
        for (int e = 0; e < 4; e++) vv[e] = sh[w][lane * 4 + e];
        int i1 = 0; float m1 = vv[0];
#pragma unroll
        for (int e = 1; e < 4; e++) if (vv[e] > m1) { m1 = vv[e]; i1 = e; }
        int i2 = -1; float m2 = -1e30f;
#pragma unroll
        for (int e = 0; e < 4; e++) if (e != i1 && vv[e] > m2) { m2 = vv[e]; i2 = e; }
#pragma unroll
        for (int e = 0; e < 4; e++)
            out[(size_t)t * 32 + lane * 4 + e] = (e == i1 || e == i2) ? vv[e] : 0.f;
    }
}

/* ------------------------------------------------------------------ */
/* Tensor-core GEMM (mma.sync), block 128x128, Kc=32, split bf16.      */
/* B side from pre-split global bf16. A side converted inline.         */
/* MODE 0: Q proj, 1: K proj, 2: V expert build, 3: O expert build     */
/* ------------------------------------------------------------------ */
#define ASTR 40
#define BSTR 136

template <int MODE>
__global__ void __launch_bounds__(256)
tc_gemm(const float* __restrict__ A,
        float* __restrict__ C) {
    constexpr int KT = (MODE <= 1) ? 1024 : 4096;

    __shared__ __nv_bfloat16 Ah[128 * ASTR];
    __shared__ __nv_bfloat16 Al[128 * ASTR];
    __shared__ __nv_bfloat16 Bh[128 * ASTR];
    __shared__ __nv_bfloat16 Bl[128 * ASTR];

    int tid = threadIdx.x;
    int warp = tid >> 5, lane = tid & 31;
    int wm = warp & 3, wn = warp >> 2;
    int row0 = blockIdx.y * 128;
    int col0 = blockIdx.x * 128;
    int hz = blockIdx.z;

    const float* gates = (MODE == 2) ? g_gv : g_go;
    const __nv_bfloat16 *Bph, *Bpl;
    if (MODE == 0)      { Bph = g_wqh; Bpl = g_wql; }
    else if (MODE == 1) { Bph = g_wkh; Bpl = g_wkl; }
    else if (MODE == 2) { Bph = g_wvh + (size_t)hz * (EE * DD * DHH);
                          Bpl = g_wvl + (size_t)hz * (EE * DD * DHH); }
    else                { Bph = g_woh; Bpl = g_wol; }

    float d[2][8][4];
#pragma unroll
    for (int i = 0; i < 2; i++)
#pragma unroll
        for (int j = 0; j < 8; j++)
#pragma unroll
            for (int c = 0; c < 4; c++) d[i][j][c] = 0.f;

    for (int k0 = 0; k0 < KT; k0 += 32) {
        /* ---- stage A (fp32 + gate -> split) ---- */
#pragma unroll
        for (int it = 0; it < 4; it++) {
            int idx = it * 256 + tid;
            int r = idx >> 3, c4 = (idx & 7) * 4;
            int kg = k0 + c4;
            int rt = row0 + r;
            const float* src;
            float gm = 1.f;
            if (MODE <= 1) {
                src = A + (size_t)rt * 1024 + kg;
            } else if (MODE == 2) {
                src = A + (size_t)rt * 1024 + (kg & 1023);
                gm = gates[(size_t)rt * 32 + hz * 4 + (kg >> 10)];
            } else {
                int hh = kg >> 9, e = (kg >> 7) & 3, dh = kg & 127;
                src = g_res + (size_t)rt * 1024 + hh * 128 + dh;
                gm = gates[(size_t)rt * 32 + hh * 4 + e];
            }
            float4 x = *(const float4*)src;
            x.x *= gm; x.y *= gm; x.z *= gm; x.w *= gm;
            uint32_t h0, l0, h1, l1;
            split_pair(x.x, x.y, h0, l0);
            split_pair(x.z, x.w, h1, l1);
            *(uint32_t*)&Ah[r * ASTR + c4] = h0;
            *(uint32_t*)&Ah[r * ASTR + c4 + 2] = h1;
            *(uint32_t*)&Al[r * ASTR + c4] = l0;
            *(uint32_t*)&Al[r * ASTR + c4 + 2] = l1;
        }
        /* ---- stage B (pre-split bf16, pure copy) ---- */
        if (MODE <= 1) {
#pragma unroll
            for (int it = 0; it < 2; it++) {
                int idx = it * 256 + tid;
                int r = idx >> 2, c8 = (idx & 3) * 8;
                size_t so = (size_t)(col0 + r) * 1024 + k0 + c8;
                *(uint4*)&Bh[r * ASTR + c8] = *(const uint4*)(Bph + so);
                *(uint4*)&Bl[r * ASTR + c8] = *(const uint4*)(Bpl + so);
            }
        } else {
            constexpr int NLD = (MODE == 2) ? 128 : 1024;
#pragma unroll
            for (int it = 0; it < 2; it++) {
                int idx = it * 256 + tid;
                int kr = idx >> 4, c8 = (idx & 15) * 8;
                size_t so = (size_t)(k0 + kr) * NLD + col0 + c8;
                *(uint4*)&Bh[kr * BSTR + c8] = *(const uint4*)(Bph + so);
                *(uint4*)&Bl[kr * BSTR + c8] = *(const uint4*)(Bpl + so);
            }
        }
        __syncthreads();

#pragma unroll
        for (int ks = 0; ks < 2; ks++) {
            uint32_t ah[2][4], al[2][4];
#pragma unroll
            for (int mf = 0; mf < 2; mf++) {
                int off = (wm * 32 + mf * 16 + (lane & 15)) * ASTR + ks * 16 + (lane >> 4) * 8;
                ldsm4(ah[mf], smem_u32(&Ah[off]));
                ldsm4(al[mf], smem_u32(&Al[off]));
            }
            uint32_t bfh[16], bfl[16];
            if (MODE <= 1) {
#pragma unroll
                for (int nf2 = 0; nf2 < 4; nf2++) {
                    int off = (wn * 64 + nf2 * 16 + (lane & 15)) * ASTR + ks * 16 + (lane >> 4) * 8;
                    uint32_t r[4];
                    ldsm4(r, smem_u32(&Bh[off]));
                    bfh[nf2 * 4 + 0] = r[0]; bfh[nf2 * 4 + 1] = r[2];
                    bfh[nf2 * 4 + 2] = r[1]; bfh[nf2 * 4 + 3] = r[3];
                    ldsm4(r, smem_u32(&Bl[off]));
                    bfl[nf2 * 4 + 0] = r[0]; bfl[nf2 * 4 + 1] = r[2];
                    bfl[nf2 * 4 + 2] = r[1]; bfl[nf2 * 4 + 3] = r[3];
                }
            } else {
#pragma unroll
                for (int nf2 = 0; nf2 < 4; nf2++) {
                    int off = (ks * 16 + (lane & 15)) * BSTR + wn * 64 + nf2 * 16 + (lane >> 4) * 8;
                    uint32_t r[4];
                    ldsm4t(r, smem_u32(&Bh[off]));
                    bfh[nf2 * 4 + 0] = r[0]; bfh[nf2 * 4 + 1] = r[1];
                    bfh[nf2 * 4 + 2] = r[2]; bfh[nf2 * 4 + 3] = r[3];
                    ldsm4t(r, smem_u32(&Bl[off]));
                    bfl[nf2 * 4 + 0] = r[0]; bfl[nf2 * 4 + 1] = r[1];
                    bfl[nf2 * 4 + 2] = r[2]; bfl[nf2 * 4 + 3] = r[3];
                }
            }
#pragma unroll
            for (int mf = 0; mf < 2; mf++)
#pragma unroll
                for (int nf = 0; nf < 8; nf++) {
                    mma16816(d[mf][nf], ah[mf], &bfh[nf * 2]);
                    mma16816(d[mf][nf], ah[mf], &bfl[nf * 2]);
                    mma16816(d[mf][nf], al[mf], &bfh[nf * 2]);
                }
        }
        __syncthreads();
    }

    /* ---- epilogue ---- */
    int ri = lane >> 2, c2 = (lane & 3) * 2;
#pragma unroll
    for (int mf = 0; mf < 2; mf++) {
#pragma unroll
        for (int nf = 0; nf < 8; nf++) {
            int col = col0 + wn * 64 + nf * 8 + c2;
#pragma unroll
            for (int hv = 0; hv < 2; hv++) {
                int row = row0 + wm * 32 + mf * 16 + ri + hv * 8;
                float v0 = d[mf][nf][hv * 2];
                float v1 = d[mf][nf][hv * 2 + 1];
                int bidx = row >> 11, sidx = row & 2047;
                if (MODE <= 1) {
                    v0 *= SCALE; v1 *= SCALE;
                    int hh = col >> 7, dh = col & 127;
                    size_t base = (((size_t)bidx * HH + hh) * SS + sidx) * DHH + dh;
                    uint32_t h, l;
                    split_pair(v0, v1, h, l);
                    __nv_bfloat16* dsth = (MODE == 0) ? g_qh : g_kh;
                    __nv_bfloat16* dstl = (MODE == 0) ? g_ql : g_kl;
                    *(uint32_t*)&dsth[base] = h;
                    *(uint32_t*)&dstl[base] = l;
                } else if (MODE == 2) {
                    size_t base = (((size_t)bidx * HH + hz) * SS + sidx) * DHH + col;
                    uint32_t h, l;
                    split_pair(v0, v1, h, l);
                    *(uint32_t*)&g_vh[base] = h;
                    *(uint32_t*)&g_vl[base] = l;
                } else {
                    float2 o = make_float2(v0, v1);
                    *(float2*)&C[(size_t)row * 1024 + col] = o;
                }
            }
        }
    }
}

/* ------------------------------------------------------------------ */
/* FA2 attention: BQ=128, BKV=64, 8 warps, Q-frags in regs,            */
/* cp.async double-buffered K/V staging, register softmax.             */
/* ------------------------------------------------------------------ */
#define KVB  8704                 /* 64*136 elems, one array */
#define BUFE (4 * KVB)            /* K/V hi/lo per buffer */
#define ATTN_BYTES (2 * BUFE * 2) /* 139264 bytes */

__device__ __forceinline__ void stage_kv(uint32_t smaddr, int bufe, int kv0, int tid,
                                         const __nv_bfloat16* kh, const __nv_bfloat16* kl,
                                         const __nv_bfloat16* vh, const __nv_bfloat16* vl) {
#pragma unroll
    for (int it = 0; it < 16; it++) {
        int idx = it * 256 + tid;
        int aid = idx >> 10;           /* constant per it */
        int rem = idx & 1023;
        int r = rem >> 4, c8 = (rem & 15) * 8;
        const __nv_bfloat16* s = (aid == 0) ? kh : (aid == 1) ? kl : (aid == 2) ? vh : vl;
        cpa16(smaddr + (uint32_t)(bufe + aid * KVB + r * 136 + c8) * 2,
              s + (size_t)(kv0 + r) * DHH + c8);
    }
}

__global__ void __launch_bounds__(256, 1) attn_fa() {
    extern __shared__ __nv_bfloat16 sm[];
    uint32_t smaddr = smem_u32(sm);

    int tid = threadIdx.x;
    int warp = tid >> 5, lane = tid & 31;
    int bh = blockIdx.y;
    int q0 = blockIdx.x * 128;

    const __nv_bfloat16* qh = g_qh + (size_t)bh * SS * DHH;
    const __nv_bfloat16* ql = g_ql + (size_t)bh * SS * DHH;
    const __nv_bfloat16* kh = g_kh + (size_t)bh * SS * DHH;
    const __nv_bfloat16* kl = g_kl + (size_t)bh * SS * DHH;
    const __nv_bfloat16* vh = g_vh + (size_t)bh * SS * DHH;
    const __nv_bfloat16* vl = g_vl + (size_t)bh * SS * DHH;

    /* ---- stage Q into buf0 space, load frags to registers ---- */
#pragma unroll
    for (int it = 0; it < 16; it++) {
        int idx = it * 256 + tid;
        int aid = idx >> 11;           /* 0 = hi, 1 = lo (constant per it) */
        int rem = idx & 2047;
        int r = rem >> 4, c8 = (rem & 15) * 8;
        const __nv_bfloat16* s = aid ? ql : qh;
        cpa16(smaddr + (uint32_t)(aid * (128 * 136) + r * 136 + c8) * 2,
              s + (size_t)(q0 + r) * DHH + c8);
    }
    CP_COMMIT();
    CP_WAIT0();
    __syncthreads();

    uint32_t qfh[8][4], qfl[8][4];
#pragma unroll
    for (int ks = 0; ks < 8; ks++) {
        int off = (warp * 16 + (lane & 15)) * 136 + ks * 16 + (lane >> 4) * 8;
        ldsm4(qfh[ks], smaddr + (uint32_t)off * 2);
        ldsm4(qfl[ks], smaddr + (uint32_t)(128 * 136 + off) * 2);
    }
    __syncthreads();

    float oacc[16][4];
#pragma unroll
    for (int j = 0; j < 16; j++)
#pragma unroll
        for (int c = 0; c < 4; c++) oacc[j][c] = 0.f;
    float mold[2] = { -1e30f, -1e30f };
    float lsum[2] = { 0.f, 0.f };

    /* prologue: stage KV tile 0 into buf0 */
    stage_kv(smaddr, 0, 0, tid, kh, kl, vh, vl);
    CP_COMMIT();

    for (int kvi = 0; kvi < SS / 64; kvi++) {
        int bufe = (kvi & 1) * BUFE;
        if (kvi + 1 < SS / 64)
            stage_kv(smaddr, ((kvi + 1) & 1) * BUFE, (kvi + 1) * 64, tid, kh, kl, vh, vl);
        CP_COMMIT();
        CP_WAIT1();
        __syncthreads();

        /* S = Q K^T : warp tile 16 x 64, K=128 */
        float sacc[8][4];
#pragma unroll
        for (int j = 0; j < 8; j++)
#pragma unroll
            for (int c = 0; c < 4; c++) sacc[j][c] = 0.f;

#pragma unroll
        for (int ks = 0; ks < 8; ks++) {
#pragma unroll
            for (int ng = 0; ng < 4; ng++) {
                int off = (ng * 16 + (lane & 15)) * 136 + ks * 16 + (lane >> 4) * 8;
                uint32_t rh[4], rl[4];
                ldsm4(rh, smaddr + (uint32_t)(bufe + off) * 2);
                ldsm4(rl, smaddr + (uint32_t)(bufe + KVB + off) * 2);
                uint32_t b0h[2] = { rh[0], rh[2] }, b1h[2] = { rh[1], rh[3] };
                uint32_t b0l[2] = { rl[0], rl[2] }, b1l[2] = { rl[1], rl[3] };
                mma16816(sacc[ng * 2], qfh[ks], b0h);
                mma16816(sacc[ng * 2], qfh[ks], b0l);
                mma16816(sacc[ng * 2], qfl[ks], b0h);
                mma16816(sacc[ng * 2 + 1], qfh[ks], b1h);
                mma16816(sacc[ng * 2 + 1], qfh[ks], b1l);
                mma16816(sacc[ng * 2 + 1], qfl[ks], b1h);
            }
        }

        /* register softmax */
        float corr[2];
#pragma unroll
        for (int hf = 0; hf < 2; hf++) {
            float mx = -1e30f;
#pragma unroll
            for (int nf = 0; nf < 8; nf++) {
                mx = fmaxf(mx, sacc[nf][hf * 2]);
                mx = fmaxf(mx, sacc[nf][hf * 2 + 1]);
            }
            mx = fmaxf(mx, __shfl_xor_sync(0xffffffffu, mx, 1));
            mx = fmaxf(mx, __shfl_xor_sync(0xffffffffu, mx, 2));
            float mnew = fmaxf(mold[hf], mx);
            corr[hf] = __expf(mold[hf] - mnew);
            mold[hf] = mnew;
            float ls = 0.f;
#pragma unroll
            for (int nf = 0; nf < 8; nf++) {
                float p0 = __expf(sacc[nf][hf * 2] - mnew);
                float p1 = __expf(sacc[nf][hf * 2 + 1] - mnew);
                sacc[nf][hf * 2] = p0;
                sacc[nf][hf * 2 + 1] = p1;
                ls += p0 + p1;
            }
            ls += __shfl_xor_sync(0xffffffffu, ls, 1);
            ls += __shfl_xor_sync(0xffffffffu, ls, 2);
            lsum[hf] = lsum[hf] * corr[hf] + ls;
        }
#pragma unroll
        for (int nf = 0; nf < 16; nf++) {
            oacc[nf][0] *= corr[0]; oacc[nf][1] *= corr[0];
            oacc[nf][2] *= corr[1]; oacc[nf][3] *= corr[1];
        }

        /* O += P V */
#pragma unroll
        for (int kk = 0; kk < 4; kk++) {
            uint32_t ph[4], pl[4];
            split_pair(sacc[kk * 2][0],     sacc[kk * 2][1],     ph[0], pl[0]);
            split_pair(sacc[kk * 2][2],     sacc[kk * 2][3],     ph[1], pl[1]);
            split_pair(sacc[kk * 2 + 1][0], sacc[kk * 2 + 1][1], ph[2], pl[2]);
            split_pair(sacc[kk * 2 + 1][2], sacc[kk * 2 + 1][3], ph[3], pl[3]);
#pragma unroll
            for (int ng = 0; ng < 8; ng++) {
                int off = (kk * 16 + (lane & 15)) * 136 + ng * 16 + (lane >> 4) * 8;
                uint32_t rh[4], rl[4];
                ldsm4t(rh, smaddr + (uint32_t)(bufe + 2 * KVB + off) * 2);
                ldsm4t(rl, smaddr + (uint32_t)(bufe + 3 * KVB + off) * 2);
                uint32_t b0h[2] = { rh[0], rh[1] }, b1h[2] = { rh[2], rh[3] };
                uint32_t b0l[2] = { rl[0], rl[1] }, b1l[2] = { rl[2], rl[3] };
                mma16816(oacc[ng * 2], ph, b0h);
                mma16816(oacc[ng * 2], ph, b0l);
                mma16816(oacc[ng * 2], pl, b0h);
                mma16816(oacc[ng * 2 + 1], ph, b1h);
                mma16816(oacc[ng * 2 + 1], ph, b1l);
                mma16816(oacc[ng * 2 + 1], pl, b1h);
            }
        }
        __syncthreads();
    }

    /* epilogue: normalize, store g_res[t, h*128+dh] */
    {
        int b = bh >> 3;
        int h2 = bh & 7;
        int ri = lane >> 2;
        int cc = (lane & 3) * 2;
        float li0 = 1.f / lsum[0];
        float li1 = 1.f / lsum[1];
        size_t t0 = (size_t)b * SS + q0 + warp * 16 + ri;
#pragma unroll
        for (int nf = 0; nf < 16; nf++) {
            int col = nf * 8 + cc;
            float2 o0 = make_float2(oacc[nf][0] * li0, oacc[nf][1] * li0);
            float2 o1 = make_float2(oacc[nf][2] * li1, oacc[nf][3] * li1);
            *(float2*)&g_res[t0 * 1024 + h2 * 128 + col] = o0;
            *(float2*)&g_res[(t0 + 8) * 1024 + h2 * 128 + col] = o1;
        }
    }
}

/* ------------------------------------------------------------------ */
extern "C" void kernel_launch(void* const* d_in, const int* in_sizes, int n_in,
                              void* d_out, int out_size) {
    (void)in_sizes; (void)n_in; (void)out_size;
    const float* q_src = (const float*)d_in[0];
    const float* k_src = (const float*)d_in[1];
    const float* v_src = (const float*)d_in[2];
    const float* Wq    = (const float*)d_in[3];
    const float* Wk    = (const float*)d_in[4];
    const float* Wv    = (const float*)d_in[5];
    const float* Wo    = (const float*)d_in[6];
    const float* sel_v = (const float*)d_in[7];
    const float* sel_o = (const float*)d_in[8];
    float* out = (float*)d_out;

    cudaFuncSetAttribute(attn_fa, cudaFuncAttributeMaxDynamicSharedMemorySize, ATTN_BYTES);

    wsplit<0><<<(DD * DD / 4 + 255) / 256, 256>>>((const float4*)Wq, DD * DD / 4);
    wsplit<1><<<(DD * DD / 4 + 255) / 256, 256>>>((const float4*)Wk, DD * DD / 4);
    wsplit<2><<<(HH * EE * DD * DHH / 4 + 255) / 256, 256>>>((const float4*)Wv, HH * EE * DD * DHH / 4);
    wsplit<3><<<(HH * EE * DHH * DD / 4 + 255) / 256, 256>>>((const float4*)Wo, HH * EE * DHH * DD / 4);
    gates_kernel<<<dim3(TOK / 8, 2), 256>>>(k_src, sel_v, q_src, sel_o);

    tc_gemm<0><<<dim3(8, 32), 256>>>(q_src, nullptr);
    tc_gemm<1><<<dim3(8, 32), 256>>>(k_src, nullptr);
    tc_gemm<2><<<dim3(1, 32, 8), 256>>>(v_src, nullptr);
    attn_fa<<<dim3(SS / 128, BB * HH), 256, ATTN_BYTES>>>();
    tc_gemm<3><<<dim3(8, 32), 256>>>(nullptr, out);
}